// round 16
// baseline (speedup 1.0000x reference)
#include <cuda_runtime.h>
#include <cuda_bf16.h>
#include <cuda_fp16.h>
#include <stdint.h>
#include <math.h>

#define BATCH  2
#define SEQ    2048
#define NHEADS 16
#define DMODEL 1024
#define DHEAD  64
#define MROWS  (BATCH*SEQ)   // 4096

// ------------------------------ scratch ------------------------------------
// Only referenced from DEVICE code (host-side refs to __device__ symbols are
// garbage addresses — R8/R9 root cause).
__device__ __align__(16) __nv_bfloat16 g_xh[(size_t)MROWS * DMODEL];
__device__ __align__(16) __nv_bfloat16 g_xl[(size_t)MROWS * DMODEL];
__device__ __align__(16) __nv_bfloat16 g_Wh[(size_t)3 * DMODEL * DMODEL]; // [3072 n][1024 k]
__device__ __align__(16) __nv_bfloat16 g_Wl[(size_t)3 * DMODEL * DMODEL];
__device__ __align__(16) __nv_bfloat16 g_Woh[(size_t)DMODEL * DMODEL];    // [1024 d][1024 c]
__device__ __align__(16) __nv_bfloat16 g_Wol[(size_t)DMODEL * DMODEL];
__device__ __align__(16) __half g_Qf[(size_t)MROWS * DMODEL];  // [token][h*64+e], pre-scaled
__device__ __align__(16) __half g_Kf[(size_t)MROWS * DMODEL];  // [token][h*64+e]
__device__ __align__(16) __half g_Vt[(size_t)MROWS * DMODEL];  // [(b*16+h)*64+e][seq]
__device__ __align__(16) __nv_bfloat16 g_Zh[(size_t)MROWS * DMODEL];
__device__ __align__(16) __nv_bfloat16 g_Zl[(size_t)MROWS * DMODEL];

// ------------------------------ helpers ------------------------------------
__device__ __forceinline__ uint32_t smem_u32(const void* p) {
    uint32_t a;
    asm("{ .reg .u64 t; cvta.to.shared.u64 t, %1; cvt.u32.u64 %0, t; }"
        : "=r"(a) : "l"(p));
    return a;
}
#define CP_ASYNC16(dst, src) \
    asm volatile("cp.async.cg.shared.global [%0], [%1], 16;" :: "r"(dst), "l"(src))
#define CP_COMMIT() asm volatile("cp.async.commit_group;" ::: "memory")

__device__ __forceinline__ void ldsm4(uint32_t r[4], uint32_t addr) {
    asm volatile("ldmatrix.sync.aligned.m8n8.x4.shared.b16 {%0,%1,%2,%3}, [%4];"
        : "=r"(r[0]), "=r"(r[1]), "=r"(r[2]), "=r"(r[3]) : "r"(addr));
}
__device__ __forceinline__ void mma_bf16(float c[4], const uint32_t a[4],
                                         uint32_t b0, uint32_t b1) {
    asm volatile(
        "mma.sync.aligned.m16n8k16.row.col.f32.bf16.bf16.f32 "
        "{%0,%1,%2,%3}, {%4,%5,%6,%7}, {%8,%9}, {%0,%1,%2,%3};"
        : "+f"(c[0]), "+f"(c[1]), "+f"(c[2]), "+f"(c[3])
        : "r"(a[0]), "r"(a[1]), "r"(a[2]), "r"(a[3]), "r"(b0), "r"(b1));
}
__device__ __forceinline__ void mma_f16(float c[4], const uint32_t a[4],
                                        uint32_t b0, uint32_t b1) {
    asm volatile(
        "mma.sync.aligned.m16n8k16.row.col.f32.f16.f16.f32 "
        "{%0,%1,%2,%3}, {%4,%5,%6,%7}, {%8,%9}, {%0,%1,%2,%3};"
        : "+f"(c[0]), "+f"(c[1]), "+f"(c[2]), "+f"(c[3])
        : "r"(a[0]), "r"(a[1]), "r"(a[2]), "r"(a[3]), "r"(b0), "r"(b1));
}
__device__ __forceinline__ void bf16_split(float v, __nv_bfloat16& hi, __nv_bfloat16& lo) {
    hi = __float2bfloat16(v);
    lo = __float2bfloat16(v - __bfloat162float(hi));
}
__device__ __forceinline__ uint32_t pack_h2(float a, float b) {
    __half2 h = __floats2half2_rn(a, b);
    return *(uint32_t*)&h;
}

// ------------------------- prep kernels -------------------------------------
__global__ __launch_bounds__(256) void convert_x_kernel(const float* __restrict__ x)
{
    int i = blockIdx.x * 256 + threadIdx.x;   // over MROWS*DMODEL/2
    float2 v = ((const float2*)x)[i];
    __nv_bfloat162 h, l;
    bf16_split(v.x, h.x, l.x);
    bf16_split(v.y, h.y, l.y);
    ((__nv_bfloat162*)g_xh)[i] = h;
    ((__nv_bfloat162*)g_xl)[i] = l;
}

// W_{Q,K,V}[h][k][e] -> g_Wh/g_Wl[(mat*1024 + h*64 + e)][k]  (z = mat*16+h)
__global__ __launch_bounds__(256) void transpose_wqkv(
    const float* __restrict__ Wq, const float* __restrict__ Wk,
    const float* __restrict__ Wv)
{
    const int z = blockIdx.z, mat = z >> 4, h = z & 15;
    const float* W = ((mat == 0) ? Wq : (mat == 1) ? Wk : Wv) + (size_t)h * DMODEL * DHEAD;
    __shared__ float t[32][33];
    const int k0 = blockIdx.x * 32, e0 = blockIdx.y * 32;
    const int tx = threadIdx.x & 31, ty = threadIdx.x >> 5;
    #pragma unroll
    for (int r = 0; r < 32; r += 8)
        t[ty + r][tx] = W[(size_t)(k0 + ty + r) * DHEAD + e0 + tx];
    __syncthreads();
    const int nbase = mat * 1024 + h * 64 + e0;
    #pragma unroll
    for (int r = 0; r < 32; r += 8) {
        float v = t[tx][ty + r];
        __nv_bfloat16 hi, lo; bf16_split(v, hi, lo);
        size_t idx = (size_t)(nbase + ty + r) * DMODEL + k0 + tx;
        g_Wh[idx] = hi; g_Wl[idx] = lo;
    }
}

// W_O flat [1024 c][1024 d] -> g_Woh/g_Wol[d][c]
__global__ __launch_bounds__(256) void transpose_wo(const float* __restrict__ Wo)
{
    __shared__ float t[32][33];
    const int d0 = blockIdx.x * 32, c0 = blockIdx.y * 32;
    const int tx = threadIdx.x & 31, ty = threadIdx.x >> 5;
    #pragma unroll
    for (int r = 0; r < 32; r += 8)
        t[ty + r][tx] = Wo[(size_t)(c0 + ty + r) * DMODEL + d0 + tx];
    __syncthreads();
    #pragma unroll
    for (int r = 0; r < 32; r += 8) {
        float v = t[tx][ty + r];
        __nv_bfloat16 hi, lo; bf16_split(v, hi, lo);
        size_t idx = (size_t)(d0 + ty + r) * DMODEL + c0 + tx;
        g_Woh[idx] = hi; g_Wol[idx] = lo;
    }
}

// ------ plane-fused mma.sync bf16-split GEMM, BM=64, 3-stage pipeline -------
// D = Ah·Bh^T + Al·Bh^T + Ah·Bl^T over K=1024; prefetch depth 2.
// mode 0: QKV  (A = x-split, B = g_Wh/g_Wl [3072][1024]) -> g_Qf/g_Kf/g_Vt fp16
// mode 1: proj (A = Z-split, B = g_Woh/g_Wol)            -> outp fp32 + b_O
#define ASTR 40                          // bf16 per smem row (80B, phase-disjoint)
#define ATILEB (64 * ASTR * 2)           // 5120 B  (A tiles: 64 rows)
#define BTILEB (128 * ASTR * 2)          // 10240 B (B tiles: 128 rows)
#define BUFB   (2 * ATILEB + 2 * BTILEB) // 30720 B per buffer
#define NSTAGE 3
#define GSMEM  (NSTAGE * BUFB)           // 92160 B

__global__ __launch_bounds__(256) void gemm_kernel(
    const float* __restrict__ b0, const float* __restrict__ b1,
    const float* __restrict__ b2, float* __restrict__ outp, int mode)
{
    extern __shared__ __align__(16) char dsm[];
    const uint32_t sbase = smem_u32(dsm);
    // per buf: [Ah 5120][Al 5120][Bh 10240][Bl 10240]
    const uint32_t tof[4] = {0u, ATILEB, 2u * ATILEB, 2u * ATILEB + BTILEB};
    auto toff = [&](int buf, int t) -> uint32_t { return sbase + buf * BUFB + tof[t]; };

    const int tid = threadIdx.x, wid = tid >> 5, lane = tid & 31;
    const int m0 = blockIdx.y * 64, n0 = blockIdx.x * 128;
    const int wm = (wid & 1) * 32, wn = (wid >> 1) * 32;   // 2x4 warp grid, 32x32 tile
    const int g  = lane >> 2;            // fragment row group
    const int kq = (lane & 3) * 2;       // fragment k-pair offset

    const __nv_bfloat16 *ah, *al, *bh, *bl;
    if (mode == 0) { ah = g_xh; al = g_xl; bh = g_Wh;  bl = g_Wl;  }
    else           { ah = g_Zh; al = g_Zl; bh = g_Woh; bl = g_Wol; }
    const int NC = 32;                   // 32 k-chunks of 32

    const int lr = tid >> 2, lseg = (tid & 3) * 8;   // loader row, k offset

    auto load_chunk = [&](int buf, int c) {
        const int k0 = c * 32;
        const uint32_t so = (lr * ASTR + lseg) * 2;
        const size_t ga = (size_t)(m0 + lr) * DMODEL + k0 + lseg;
        CP_ASYNC16(toff(buf, 0) + so, ah + ga);
        CP_ASYNC16(toff(buf, 1) + so, al + ga);
        #pragma unroll
        for (int it = 0; it < 2; it++) {
            const int r = lr + it * 64;
            const size_t gb = (size_t)(n0 + r) * DMODEL + k0 + lseg;
            const uint32_t sb = ((r)*ASTR + lseg) * 2;
            CP_ASYNC16(toff(buf, 2) + sb, bh + gb);
            CP_ASYNC16(toff(buf, 3) + sb, bl + gb);
        }
        CP_COMMIT();
    };

    float C[2][4][4];
    #pragma unroll
    for (int i = 0; i < 2; i++)
        #pragma unroll
        for (int j = 0; j < 4; j++)
            #pragma unroll
            for (int q = 0; q < 4; q++) C[i][j][q] = 0.0f;

    // ldmatrix per-lane address pieces: row-in-16 = lane&15, k-half = (lane>>4)*8
    const int lrow = lane & 15, lcol = (lane >> 4) * 8;

    load_chunk(0, 0);
    load_chunk(1, 1);

    for (int c = 0; c < NC; c++) {
        const int buf = c % NSTAGE;
        // wait: at most 1 group pending -> chunk c complete (c+1 may remain)
        asm volatile("cp.async.wait_group 1;" ::: "memory");
        __syncthreads();                 // chunk c visible; buf (c+2)%3 free
        if (c + 2 < NC) load_chunk((c + 2) % NSTAGE, c + 2);

        #pragma unroll
        for (int ks = 0; ks < 2; ks++) {
            const uint32_t fo = (ks * 16 + lcol) * 2;   // frag k-byte offset
            uint32_t arh[2][4], brh[2][4], t[2][4];
            // Ah, Bh frags
            #pragma unroll
            for (int i = 0; i < 2; i++)
                ldsm4(arh[i], toff(buf, 0) + ((wm + i * 16 + lrow) * ASTR) * 2 + fo);
            #pragma unroll
            for (int j16 = 0; j16 < 2; j16++)
                ldsm4(brh[j16], toff(buf, 2) + ((wn + j16 * 16 + lrow) * ASTR) * 2 + fo);
            // plane 0: Ah·Bh
            #pragma unroll
            for (int i = 0; i < 2; i++)
                #pragma unroll
                for (int j = 0; j < 4; j++)
                    mma_bf16(C[i][j], arh[i], brh[j >> 1][j & 1], brh[j >> 1][(j & 1) + 2]);
            // plane 1: Al·Bh (t = Al frags)
            #pragma unroll
            for (int i = 0; i < 2; i++)
                ldsm4(t[i], toff(buf, 1) + ((wm + i * 16 + lrow) * ASTR) * 2 + fo);
            #pragma unroll
            for (int i = 0; i < 2; i++)
                #pragma unroll
                for (int j = 0; j < 4; j++)
                    mma_bf16(C[i][j], t[i], brh[j >> 1][j & 1], brh[j >> 1][(j & 1) + 2]);
            // plane 2: Ah·Bl (t = Bl frags)
            #pragma unroll
            for (int j16 = 0; j16 < 2; j16++)
                ldsm4(t[j16], toff(buf, 3) + ((wn + j16 * 16 + lrow) * ASTR) * 2 + fo);
            #pragma unroll
            for (int i = 0; i < 2; i++)
                #pragma unroll
                for (int j = 0; j < 4; j++)
                    mma_bf16(C[i][j], arh[i], t[j >> 1][j & 1], t[j >> 1][(j & 1) + 2]);
        }
    }

    // ----- epilogue -----
    const int er = m0 + wm + g;
    const int ec = wn + kq;

    if (mode == 1) {
        #pragma unroll
        for (int i = 0; i < 2; i++) {
            #pragma unroll
            for (int j = 0; j < 4; j++) {
                const int col = n0 + ec + j * 8;
                const float bx = b0[col], by = b0[col + 1];
                const int row = er + i * 16;
                *(float2*)&outp[(size_t)row * DMODEL + col] =
                    make_float2(C[i][j][0] + bx, C[i][j][1] + by);
                *(float2*)&outp[(size_t)(row + 8) * DMODEL + col] =
                    make_float2(C[i][j][2] + bx, C[i][j][3] + by);
            }
        }
        return;
    }

    const int mat  = n0 >> 10;
    const int col0 = n0 & 1023;
    const float scale = (mat == 0) ? 0.125f : 1.0f;
    const float* bias = (mat == 0) ? b0 : (mat == 1) ? b1 : b2;

    #pragma unroll
    for (int i = 0; i < 2; i++) {
        #pragma unroll
        for (int j = 0; j < 4; j++) {
            const int col = col0 + ec + j * 8;
            const float bx = bias[col], by = bias[col + 1];
            const int row0 = er + i * 16, row1 = row0 + 8;
            const float v00 = (C[i][j][0] + bx) * scale;
            const float v01 = (C[i][j][1] + by) * scale;
            const float v10 = (C[i][j][2] + bx) * scale;
            const float v11 = (C[i][j][3] + by) * scale;
            if (mat == 0) {
                *(__half2*)&g_Qf[(size_t)row0 * DMODEL + col] = __floats2half2_rn(v00, v01);
                *(__half2*)&g_Qf[(size_t)row1 * DMODEL + col] = __floats2half2_rn(v10, v11);
            } else if (mat == 1) {
                *(__half2*)&g_Kf[(size_t)row0 * DMODEL + col] = __floats2half2_rn(v00, v01);
                *(__half2*)&g_Kf[(size_t)row1 * DMODEL + col] = __floats2half2_rn(v10, v11);
            } else {
                // V transposed: [(b*16+h)*64+e][seq]
                const int bb = row0 >> 11, s0 = row0 & 2047, s1 = s0 + 8;
                const int hh = col >> 6, e = col & 63;
                const size_t base = ((size_t)((bb * NHEADS + hh) * 64 + e)) * SEQ;
                g_Vt[base + s0]       = __float2half(v00);
                g_Vt[base + SEQ + s0] = __float2half(v01);   // e+1
                g_Vt[base + s1]       = __float2half(v10);
                g_Vt[base + SEQ + s1] = __float2half(v11);
            }
        }
    }
}

// ------------------------- fp16 mma flash attention -------------------------
// CTA = (qt, h, b): 64 queries, 4 warps x 16 rows. S and P live in fragments.
#define QSTR 72   // fp16 elems per smem row (36 words: conflict-free frag loads)

__global__ __launch_bounds__(128) void attn_kernel()
{
    __shared__ __align__(16) __half Qs[64 * QSTR];
    __shared__ __align__(16) __half Ks[64 * QSTR];
    __shared__ __align__(16) __half Vs[64 * QSTR];   // Vt tile: [d][key]

    const int qt = blockIdx.x, h = blockIdx.y, b = blockIdx.z;
    const int tid = threadIdx.x, w = tid >> 5, lane = tid & 31;
    const int g = lane >> 2, kq = (lane & 3) * 2;
    const int q0 = qt * 64;

    // Q tile load: 64 rows x 8 16B-segs = 512 slots
    #pragma unroll
    for (int it = 0; it < 4; it++) {
        const int s = tid + it * 128, r = s >> 3, seg = s & 7;
        *(uint4*)&Qs[r * QSTR + seg * 8] =
            *(const uint4*)(g_Qf + (size_t)(b * SEQ + q0 + r) * DMODEL + h * 64 + seg * 8);
    }

    uint4 kvr[4], vvr[4];
    auto load_regs = [&](int kt) {
        const int k0 = kt * 64;
        #pragma unroll
        for (int it = 0; it < 4; it++) {
            const int s = tid + it * 128, r = s >> 3, seg = s & 7;
            kvr[it] = *(const uint4*)(g_Kf + (size_t)(b * SEQ + k0 + r) * DMODEL + h * 64 + seg * 8);
            vvr[it] = *(const uint4*)(g_Vt + ((size_t)((b * NHEADS + h) * 64 + r)) * SEQ + k0 + seg * 8);
        }
    };
    auto store_smem = [&]() {
        #pragma unroll
        for (int it = 0; it < 4; it++) {
            const int s = tid + it * 128, r = s >> 3, seg = s & 7;
            *(uint4*)&Ks[r * QSTR + seg * 8] = kvr[it];
            *(uint4*)&Vs[r * QSTR + seg * 8] = vvr[it];
        }
    };

    float m_run[2] = {-1e30f, -1e30f};
    float l_run[2] = {0.0f, 0.0f};
    float Z[8][4];
    #pragma unroll
    for (int j = 0; j < 8; j++)
        #pragma unroll
        for (int q = 0; q < 4; q++) Z[j][q] = 0.0f;

    load_regs(0);

    for (int kt = 0; kt <= qt; kt++) {
        store_smem();
        __syncthreads();
        if (kt < qt) load_regs(kt + 1);

        // ---- S = Q K^T ----
        float S[8][4];
        #pragma unroll
        for (int j = 0; j < 8; j++)
            #pragma unroll
            for (int q = 0; q < 4; q++) S[j][q] = 0.0f;

        #pragma unroll
        for (int ks = 0; ks < 4; ks++) {
            const int kc = ks * 16 + kq;
            const int row = w * 16 + g;
            uint32_t a[4];
            a[0] = *(const uint32_t*)&Qs[(row)     * QSTR + kc];
            a[1] = *(const uint32_t*)&Qs[(row + 8) * QSTR + kc];
            a[2] = *(const uint32_t*)&Qs[(row)     * QSTR + kc + 8];
            a[3] = *(const uint32_t*)&Qs[(row + 8) * QSTR + kc + 8];
            #pragma unroll
            for (int j = 0; j < 8; j++) {
                const int nrow = j * 8 + g;
                const uint32_t bb0 = *(const uint32_t*)&Ks[nrow * QSTR + kc];
                const uint32_t bb1 = *(const uint32_t*)&Ks[nrow * QSTR + kc + 8];
                mma_f16(S[j], a, bb0, bb1);
            }
        }

        // ---- causal mask (diagonal tile only) ----
        if (kt == qt) {
            const int r0 = w * 16 + g, r1 = r0 + 8;
            #pragma unroll
            for (int j = 0; j < 8; j++) {
                const int c0 = j * 8 + kq, c1 = c0 + 1;
                if (c0 > r0) S[j][0] = -1e30f;
                if (c1 > r0) S[j][1] = -1e30f;
                if (c0 > r1) S[j][2] = -1e30f;
                if (c1 > r1) S[j][3] = -1e30f;
            }
        }

        // ---- online softmax on fragments (rows r0, r1 per thread) ----
        float mx0 = -1e30f, mx1 = -1e30f;
        #pragma unroll
        for (int j = 0; j < 8; j++) {
            mx0 = fmaxf(mx0, fmaxf(S[j][0], S[j][1]));
            mx1 = fmaxf(mx1, fmaxf(S[j][2], S[j][3]));
        }
        mx0 = fmaxf(mx0, __shfl_xor_sync(0xffffffffu, mx0, 1));
        mx0 = fmaxf(mx0, __shfl_xor_sync(0xffffffffu, mx0, 2));
        mx1 = fmaxf(mx1, __shfl_xor_sync(0xffffffffu, mx1, 1));
        mx1 = fmaxf(mx1, __shfl_xor_sync(0xffffffffu, mx1, 2));

        const float mn0 = fmaxf(m_run[0], mx0);
        const float mn1 = fmaxf(m_run[1], mx1);
        const float al0 = __expf(m_run[0] - mn0);
        const float al1 = __expf(m_run[1] - mn1);
        float sum0 = 0.0f, sum1 = 0.0f;
        #pragma unroll
        for (int j = 0; j < 8; j++) {
            S[j][0] = __expf(S[j][0] - mn0); sum0 += S[j][0];
            S[j][1] = __expf(S[j][1] - mn0); sum0 += S[j][1];
            S[j][2] = __expf(S[j][2] - mn1); sum1 += S[j][2];
            S[j][3] = __expf(S[j][3] - mn1); sum1 += S[j][3];
        }
        sum0 += __shfl_xor_sync(0xffffffffu, sum0, 1);
        sum0 += __shfl_xor_sync(0xffffffffu, sum0, 2);
        sum1 += __shfl_xor_sync(0xffffffffu, sum1, 1);
        sum1 += __shfl_xor_sync(0xffffffffu, sum1, 2);

        l_run[0] = l_run[0] * al0 + sum0;  m_run[0] = mn0;
        l_run[1] = l_run[1] * al1 + sum1;  m_run[1] = mn1;

        #pragma unroll
        for (int j = 0; j < 8; j++) {
            Z[j][0] *= al0; Z[j][1] *= al0;
            Z[j][2] *= al1; Z[j][3] *= al1;
        }

        // ---- Z += P V : repack S c-frags into a-frags (pure register) ----
        #pragma unroll
        for (int jj = 0; jj < 4; jj++) {
            uint32_t a[4];
            a[0] = pack_h2(S[2*jj][0],     S[2*jj][1]);
            a[1] = pack_h2(S[2*jj][2],     S[2*jj][3]);
            a[2] = pack_h2(S[2*jj + 1][0], S[2*jj + 1][1]);
            a[3] = pack_h2(S[2*jj + 1][2], S[2*jj + 1][3]);
            const int kc = jj * 16 + kq;
            #pragma unroll
            for (int j = 0; j < 8; j++) {
                const int nrow = j * 8 + g;
                const uint32_t bb0 = *(const uint32_t*)&Vs[nrow * QSTR + kc];
                const uint32_t bb1 = *(const uint32_t*)&Vs[nrow * QSTR + kc + 8];
                mma_f16(Z[j], a, bb0, bb1);
            }
        }
        __syncthreads();
    }

    // ---- epilogue: normalize + split-bf16 Z ----
    const float inv0 = 1.0f / l_run[0];
    const float inv1 = 1.0f / l_run[1];
    const int r0 = q0 + w * 16 + g, r1 = r0 + 8;
    #pragma unroll
    for (int j = 0; j < 8; j++) {
        const int col = h * 64 + j * 8 + kq;
        const size_t i0 = (size_t)(b * SEQ + r0) * DMODEL + col;
        const size_t i1 = (size_t)(b * SEQ + r1) * DMODEL + col;
        __nv_bfloat16 hi, lo;
        bf16_split(Z[j][0] * inv0, hi, lo); g_Zh[i0]     = hi; g_Zl[i0]     = lo;
        bf16_split(Z[j][1] * inv0, hi, lo); g_Zh[i0 + 1] = hi; g_Zl[i0 + 1] = lo;
        bf16_split(Z[j][2] * inv1, hi, lo); g_Zh[i1]     = hi; g_Zl[i1]     = lo;
        bf16_split(Z[j][3] * inv1, hi, lo); g_Zh[i1 + 1] = hi; g_Zl[i1 + 1] = lo;
    }
}

// ------------------------------ launch --------------------------------------
extern "C" void kernel_launch(void* const* d_in, const int* in_sizes, int n_in,
                              void* d_out, int out_size)
{
    (void)in_sizes; (void)n_in; (void)out_size;
    const float* x  = (const float*)d_in[0];
    const float* Wq = (const float*)d_in[1];
    const float* Wk = (const float*)d_in[2];
    const float* Wv = (const float*)d_in[3];
    const float* Wo = (const float*)d_in[4];
    const float* bq = (const float*)d_in[5];
    const float* bk = (const float*)d_in[6];
    const float* bv = (const float*)d_in[7];
    const float* bo = (const float*)d_in[8];
    float* out = (float*)d_out;

    cudaFuncSetAttribute(gemm_kernel,
                         cudaFuncAttributeMaxDynamicSharedMemorySize, GSMEM);

    convert_x_kernel<<<(MROWS * DMODEL / 2) / 256, 256>>>(x);
    transpose_wqkv<<<dim3(32, 2, 48), 256>>>(Wq, Wk, Wv);
    transpose_wo<<<dim3(32, 32), 256>>>(Wo);

    gemm_kernel<<<dim3(24, 64), 256, GSMEM>>>(bq, bk, bv, nullptr, 0);

    attn_kernel<<<dim3(SEQ / 64, NHEADS, BATCH), 128>>>();

    gemm_kernel<<<dim3(8, 64), 256, GSMEM>>>(bo, bo, bo, out, 1);
}

// round 17
// speedup vs baseline: 1.0673x; 1.0673x over previous
#include <cuda_runtime.h>
#include <cuda_bf16.h>
#include <cuda_fp16.h>
#include <stdint.h>
#include <math.h>

#define BATCH  2
#define SEQ    2048
#define NHEADS 16
#define DMODEL 1024
#define DHEAD  64
#define MROWS  (BATCH*SEQ)   // 4096

// ------------------------------ scratch ------------------------------------
// Only referenced from DEVICE code (host-side refs to __device__ symbols are
// garbage addresses — R8/R9 root cause).
__device__ __align__(16) __nv_bfloat16 g_xh[(size_t)MROWS * DMODEL];
__device__ __align__(16) __nv_bfloat16 g_xl[(size_t)MROWS * DMODEL];
__device__ __align__(16) __nv_bfloat16 g_Wh[(size_t)3 * DMODEL * DMODEL]; // [3072 n][1024 k]
__device__ __align__(16) __nv_bfloat16 g_Wl[(size_t)3 * DMODEL * DMODEL];
__device__ __align__(16) __nv_bfloat16 g_Woh[(size_t)DMODEL * DMODEL];    // [1024 d][1024 c]
__device__ __align__(16) __nv_bfloat16 g_Wol[(size_t)DMODEL * DMODEL];
__device__ __align__(16) __half g_Qf[(size_t)MROWS * DMODEL];  // [token][h*64+e], pre-scaled
__device__ __align__(16) __half g_Kf[(size_t)MROWS * DMODEL];  // [token][h*64+e]
__device__ __align__(16) __half g_Vt[(size_t)MROWS * DMODEL];  // [(b*16+h)*64+e][seq]
__device__ __align__(16) __nv_bfloat16 g_Zh[(size_t)MROWS * DMODEL];
__device__ __align__(16) __nv_bfloat16 g_Zl[(size_t)MROWS * DMODEL];

// ------------------------------ helpers ------------------------------------
__device__ __forceinline__ uint32_t smem_u32(const void* p) {
    uint32_t a;
    asm("{ .reg .u64 t; cvta.to.shared.u64 t, %1; cvt.u32.u64 %0, t; }"
        : "=r"(a) : "l"(p));
    return a;
}
#define CP_ASYNC16(dst, src) \
    asm volatile("cp.async.cg.shared.global [%0], [%1], 16;" :: "r"(dst), "l"(src))
#define CP_COMMIT() asm volatile("cp.async.commit_group;" ::: "memory")

__device__ __forceinline__ void ldsm4(uint32_t r[4], uint32_t addr) {
    asm volatile("ldmatrix.sync.aligned.m8n8.x4.shared.b16 {%0,%1,%2,%3}, [%4];"
        : "=r"(r[0]), "=r"(r[1]), "=r"(r[2]), "=r"(r[3]) : "r"(addr));
}
__device__ __forceinline__ void mma_bf16(float c[4], const uint32_t a[4],
                                         uint32_t b0, uint32_t b1) {
    asm volatile(
        "mma.sync.aligned.m16n8k16.row.col.f32.bf16.bf16.f32 "
        "{%0,%1,%2,%3}, {%4,%5,%6,%7}, {%8,%9}, {%0,%1,%2,%3};"
        : "+f"(c[0]), "+f"(c[1]), "+f"(c[2]), "+f"(c[3])
        : "r"(a[0]), "r"(a[1]), "r"(a[2]), "r"(a[3]), "r"(b0), "r"(b1));
}
__device__ __forceinline__ void mma_f16(float c[4], const uint32_t a[4],
                                        uint32_t b0, uint32_t b1) {
    asm volatile(
        "mma.sync.aligned.m16n8k16.row.col.f32.f16.f16.f32 "
        "{%0,%1,%2,%3}, {%4,%5,%6,%7}, {%8,%9}, {%0,%1,%2,%3};"
        : "+f"(c[0]), "+f"(c[1]), "+f"(c[2]), "+f"(c[3])
        : "r"(a[0]), "r"(a[1]), "r"(a[2]), "r"(a[3]), "r"(b0), "r"(b1));
}
__device__ __forceinline__ void bf16_split(float v, __nv_bfloat16& hi, __nv_bfloat16& lo) {
    hi = __float2bfloat16(v);
    lo = __float2bfloat16(v - __bfloat162float(hi));
}
__device__ __forceinline__ uint32_t pack_h2(float a, float b) {
    __half2 h = __floats2half2_rn(a, b);
    return *(uint32_t*)&h;
}

// ------------------------- prep kernels -------------------------------------
__global__ __launch_bounds__(256) void convert_x_kernel(const float* __restrict__ x)
{
    int i = blockIdx.x * 256 + threadIdx.x;   // over MROWS*DMODEL/2
    float2 v = ((const float2*)x)[i];
    __nv_bfloat162 h, l;
    bf16_split(v.x, h.x, l.x);
    bf16_split(v.y, h.y, l.y);
    ((__nv_bfloat162*)g_xh)[i] = h;
    ((__nv_bfloat162*)g_xl)[i] = l;
}

// W_{Q,K,V}[h][k][e] -> g_Wh/g_Wl[(mat*1024 + h*64 + e)][k]  (z = mat*16+h)
__global__ __launch_bounds__(256) void transpose_wqkv(
    const float* __restrict__ Wq, const float* __restrict__ Wk,
    const float* __restrict__ Wv)
{
    const int z = blockIdx.z, mat = z >> 4, h = z & 15;
    const float* W = ((mat == 0) ? Wq : (mat == 1) ? Wk : Wv) + (size_t)h * DMODEL * DHEAD;
    __shared__ float t[32][33];
    const int k0 = blockIdx.x * 32, e0 = blockIdx.y * 32;
    const int tx = threadIdx.x & 31, ty = threadIdx.x >> 5;
    #pragma unroll
    for (int r = 0; r < 32; r += 8)
        t[ty + r][tx] = W[(size_t)(k0 + ty + r) * DHEAD + e0 + tx];
    __syncthreads();
    const int nbase = mat * 1024 + h * 64 + e0;
    #pragma unroll
    for (int r = 0; r < 32; r += 8) {
        float v = t[tx][ty + r];
        __nv_bfloat16 hi, lo; bf16_split(v, hi, lo);
        size_t idx = (size_t)(nbase + ty + r) * DMODEL + k0 + tx;
        g_Wh[idx] = hi; g_Wl[idx] = lo;
    }
}

// W_O flat [1024 c][1024 d] -> g_Woh/g_Wol[d][c]
__global__ __launch_bounds__(256) void transpose_wo(const float* __restrict__ Wo)
{
    __shared__ float t[32][33];
    const int d0 = blockIdx.x * 32, c0 = blockIdx.y * 32;
    const int tx = threadIdx.x & 31, ty = threadIdx.x >> 5;
    #pragma unroll
    for (int r = 0; r < 32; r += 8)
        t[ty + r][tx] = Wo[(size_t)(c0 + ty + r) * DMODEL + d0 + tx];
    __syncthreads();
    #pragma unroll
    for (int r = 0; r < 32; r += 8) {
        float v = t[tx][ty + r];
        __nv_bfloat16 hi, lo; bf16_split(v, hi, lo);
        size_t idx = (size_t)(d0 + ty + r) * DMODEL + c0 + tx;
        g_Woh[idx] = hi; g_Wol[idx] = lo;
    }
}

// ------------- plane-fused mma.sync bf16-split GEMM (best: R14) -------------
// D = Ah·Bh^T + Al·Bh^T + Ah·Bl^T over K=1024; 128x128 tile, 2-stage.
// mode 0: QKV  (A = x-split, B = g_Wh/g_Wl [3072][1024]) -> g_Qf/g_Kf/g_Vt fp16
// mode 1: proj (A = Z-split, B = g_Woh/g_Wol)            -> outp fp32 + b_O
#define ASTR 40                         // bf16 per smem row (80B, phase-disjoint)
#define TILEB (128 * ASTR * 2)          // 10240 B per tile
#define GSMEM (8 * TILEB)               // 2 bufs x 4 tiles = 81920 B

__global__ __launch_bounds__(256) void gemm_kernel(
    const float* __restrict__ b0, const float* __restrict__ b1,
    const float* __restrict__ b2, float* __restrict__ outp, int mode)
{
    extern __shared__ __align__(16) char dsm[];
    const uint32_t sbase = smem_u32(dsm);
    // layout per buf: [Ah][Al][Bh][Bl]
    auto toff = [&](int buf, int t) -> uint32_t { return sbase + (buf * 4 + t) * TILEB; };

    const int tid = threadIdx.x, wid = tid >> 5, lane = tid & 31;
    const int m0 = blockIdx.y * 128, n0 = blockIdx.x * 128;
    const int wm = (wid & 3) * 32, wn = (wid >> 2) * 64;
    const int g  = lane >> 2;            // fragment row group
    const int kq = (lane & 3) * 2;       // fragment k-pair offset

    const __nv_bfloat16 *ah, *al, *bh, *bl;
    if (mode == 0) { ah = g_xh; al = g_xl; bh = g_Wh;  bl = g_Wl;  }
    else           { ah = g_Zh; al = g_Zl; bh = g_Woh; bl = g_Wol; }
    const int NC = 32;                   // 32 k-chunks of 32

    const int lr0 = tid >> 2, lseg = (tid & 3) * 8;   // loader row, k offset

    auto load_chunk = [&](int buf, int c) {
        const int k0 = c * 32;
        #pragma unroll
        for (int it = 0; it < 2; it++) {
            const int r = lr0 + it * 64;
            const uint32_t so = (r * ASTR + lseg) * 2;
            const size_t ga = (size_t)(m0 + r) * DMODEL + k0 + lseg;
            const size_t gb = (size_t)(n0 + r) * DMODEL + k0 + lseg;
            CP_ASYNC16(toff(buf, 0) + so, ah + ga);
            CP_ASYNC16(toff(buf, 1) + so, al + ga);
            CP_ASYNC16(toff(buf, 2) + so, bh + gb);
            CP_ASYNC16(toff(buf, 3) + so, bl + gb);
        }
        CP_COMMIT();
    };

    float C[2][8][4];
    #pragma unroll
    for (int i = 0; i < 2; i++)
        #pragma unroll
        for (int j = 0; j < 8; j++)
            #pragma unroll
            for (int q = 0; q < 4; q++) C[i][j][q] = 0.0f;

    // ldmatrix per-lane address pieces: row-in-16 = lane&15, k-half = (lane>>4)*8
    const int lrow = lane & 15, lcol = (lane >> 4) * 8;

    load_chunk(0, 0);

    for (int c = 0; c < NC; c++) {
        const int buf = c & 1;
        asm volatile("cp.async.wait_group 0;" ::: "memory");
        __syncthreads();                        // chunk c visible; buf^1 free
        if (c + 1 < NC) load_chunk(buf ^ 1, c + 1);

        #pragma unroll
        for (int ks = 0; ks < 2; ks++) {
            const uint32_t fo = (ks * 16 + lcol) * 2;   // frag k-byte offset
            uint32_t arh[2][4], brh[4][4], t[4][4];
            // Ah, Bh frags
            #pragma unroll
            for (int i = 0; i < 2; i++)
                ldsm4(arh[i], toff(buf, 0) + ((wm + i * 16 + lrow) * ASTR) * 2 + fo);
            #pragma unroll
            for (int j16 = 0; j16 < 4; j16++)
                ldsm4(brh[j16], toff(buf, 2) + ((wn + j16 * 16 + lrow) * ASTR) * 2 + fo);
            // plane 0: Ah·Bh
            #pragma unroll
            for (int i = 0; i < 2; i++)
                #pragma unroll
                for (int j = 0; j < 8; j++)
                    mma_bf16(C[i][j], arh[i], brh[j >> 1][j & 1], brh[j >> 1][(j & 1) + 2]);
            // plane 1: Al·Bh (t = Al frags)
            #pragma unroll
            for (int i = 0; i < 2; i++)
                ldsm4(t[i], toff(buf, 1) + ((wm + i * 16 + lrow) * ASTR) * 2 + fo);
            #pragma unroll
            for (int i = 0; i < 2; i++)
                #pragma unroll
                for (int j = 0; j < 8; j++)
                    mma_bf16(C[i][j], t[i], brh[j >> 1][j & 1], brh[j >> 1][(j & 1) + 2]);
            // plane 2: Ah·Bl (t = Bl frags)
            #pragma unroll
            for (int j16 = 0; j16 < 4; j16++)
                ldsm4(t[j16], toff(buf, 3) + ((wn + j16 * 16 + lrow) * ASTR) * 2 + fo);
            #pragma unroll
            for (int i = 0; i < 2; i++)
                #pragma unroll
                for (int j = 0; j < 8; j++)
                    mma_bf16(C[i][j], arh[i], t[j >> 1][j & 1], t[j >> 1][(j & 1) + 2]);
        }
        __syncthreads();
    }

    // ----- epilogue -----
    const int er = m0 + wm + g;
    const int ec = wn + kq;

    if (mode == 1) {
        #pragma unroll
        for (int i = 0; i < 2; i++) {
            #pragma unroll
            for (int j = 0; j < 8; j++) {
                const int col = n0 + ec + j * 8;
                const float bx = b0[col], by = b0[col + 1];
                const int row = er + i * 16;
                *(float2*)&outp[(size_t)row * DMODEL + col] =
                    make_float2(C[i][j][0] + bx, C[i][j][1] + by);
                *(float2*)&outp[(size_t)(row + 8) * DMODEL + col] =
                    make_float2(C[i][j][2] + bx, C[i][j][3] + by);
            }
        }
        return;
    }

    const int mat  = n0 >> 10;
    const int col0 = n0 & 1023;
    const float scale = (mat == 0) ? 0.125f : 1.0f;
    const float* bias = (mat == 0) ? b0 : (mat == 1) ? b1 : b2;

    #pragma unroll
    for (int i = 0; i < 2; i++) {
        #pragma unroll
        for (int j = 0; j < 8; j++) {
            const int col = col0 + ec + j * 8;
            const float bx = bias[col], by = bias[col + 1];
            const int row0 = er + i * 16, row1 = row0 + 8;
            const float v00 = (C[i][j][0] + bx) * scale;
            const float v01 = (C[i][j][1] + by) * scale;
            const float v10 = (C[i][j][2] + bx) * scale;
            const float v11 = (C[i][j][3] + by) * scale;
            if (mat == 0) {
                *(__half2*)&g_Qf[(size_t)row0 * DMODEL + col] = __floats2half2_rn(v00, v01);
                *(__half2*)&g_Qf[(size_t)row1 * DMODEL + col] = __floats2half2_rn(v10, v11);
            } else if (mat == 1) {
                *(__half2*)&g_Kf[(size_t)row0 * DMODEL + col] = __floats2half2_rn(v00, v01);
                *(__half2*)&g_Kf[(size_t)row1 * DMODEL + col] = __floats2half2_rn(v10, v11);
            } else {
                // V transposed: [(b*16+h)*64+e][seq]
                const int bb = row0 >> 11, s0 = row0 & 2047, s1 = s0 + 8;
                const int hh = col >> 6, e = col & 63;
                const size_t base = ((size_t)((bb * NHEADS + hh) * 64 + e)) * SEQ;
                g_Vt[base + s0]       = __float2half(v00);
                g_Vt[base + SEQ + s0] = __float2half(v01);   // e+1
                g_Vt[base + s1]       = __float2half(v10);
                g_Vt[base + SEQ + s1] = __float2half(v11);
            }
        }
    }
}

// ------------------------- fp16 mma flash attention -------------------------
// CTA = (qt, h, b): 128 queries, 8 warps x 16 rows, 256 threads.
// K/V tiles (64 keys) are loaded once and reused by all 8 warps.
#define QSTR 72   // fp16 elems per smem row (36 words: conflict-free frag loads)

__global__ __launch_bounds__(256) void attn_kernel()
{
    __shared__ __align__(16) __half Qs[128 * QSTR];
    __shared__ __align__(16) __half Ks[64 * QSTR];
    __shared__ __align__(16) __half Vs[64 * QSTR];   // Vt tile: [d][key]

    const int qt = blockIdx.x, h = blockIdx.y, b = blockIdx.z;
    const int tid = threadIdx.x, w = tid >> 5, lane = tid & 31;
    const int g = lane >> 2, kq = (lane & 3) * 2;
    const int q0 = qt * 128;

    // Q tile load: 128 rows x 8 16B-segs = 1024 slots
    #pragma unroll
    for (int it = 0; it < 4; it++) {
        const int s = tid + it * 256, r = s >> 3, seg = s & 7;
        *(uint4*)&Qs[r * QSTR + seg * 8] =
            *(const uint4*)(g_Qf + (size_t)(b * SEQ + q0 + r) * DMODEL + h * 64 + seg * 8);
    }

    uint4 kvr[2], vvr[2];
    auto load_regs = [&](int kt) {
        const int k0 = kt * 64;
        #pragma unroll
        for (int it = 0; it < 2; it++) {
            const int s = tid + it * 256, r = s >> 3, seg = s & 7;
            kvr[it] = *(const uint4*)(g_Kf + (size_t)(b * SEQ + k0 + r) * DMODEL + h * 64 + seg * 8);
            vvr[it] = *(const uint4*)(g_Vt + ((size_t)((b * NHEADS + h) * 64 + r)) * SEQ + k0 + seg * 8);
        }
    };
    auto store_smem = [&]() {
        #pragma unroll
        for (int it = 0; it < 2; it++) {
            const int s = tid + it * 256, r = s >> 3, seg = s & 7;
            *(uint4*)&Ks[r * QSTR + seg * 8] = kvr[it];
            *(uint4*)&Vs[r * QSTR + seg * 8] = vvr[it];
        }
    };

    float m_run[2] = {-1e30f, -1e30f};
    float l_run[2] = {0.0f, 0.0f};
    float Z[8][4];
    #pragma unroll
    for (int j = 0; j < 8; j++)
        #pragma unroll
        for (int q = 0; q < 4; q++) Z[j][q] = 0.0f;

    const int NT = 2 * qt + 2;           // 64-key tiles covering keys <= q0+127
    load_regs(0);

    for (int kt = 0; kt < NT; kt++) {
        store_smem();
        __syncthreads();
        if (kt + 1 < NT) load_regs(kt + 1);

        // ---- S = Q K^T ----
        float S[8][4];
        #pragma unroll
        for (int j = 0; j < 8; j++)
            #pragma unroll
            for (int q = 0; q < 4; q++) S[j][q] = 0.0f;

        #pragma unroll
        for (int ks = 0; ks < 4; ks++) {
            const int kc = ks * 16 + kq;
            const int row = w * 16 + g;
            uint32_t a[4];
            a[0] = *(const uint32_t*)&Qs[(row)     * QSTR + kc];
            a[1] = *(const uint32_t*)&Qs[(row + 8) * QSTR + kc];
            a[2] = *(const uint32_t*)&Qs[(row)     * QSTR + kc + 8];
            a[3] = *(const uint32_t*)&Qs[(row + 8) * QSTR + kc + 8];
            #pragma unroll
            for (int j = 0; j < 8; j++) {
                const int nrow = j * 8 + g;
                const uint32_t bb0 = *(const uint32_t*)&Ks[nrow * QSTR + kc];
                const uint32_t bb1 = *(const uint32_t*)&Ks[nrow * QSTR + kc + 8];
                mma_f16(S[j], a, bb0, bb1);
            }
        }

        // ---- causal mask (only tiles that can cross the diagonal) ----
        const int r0g = q0 + w * 16 + g;     // global rows handled by thread
        const int r1g = r0g + 8;
        const int kbase = kt * 64;
        if (kbase + 63 > r0g) {              // any key could exceed a row
            #pragma unroll
            for (int j = 0; j < 8; j++) {
                const int c0 = kbase + j * 8 + kq, c1 = c0 + 1;
                if (c0 > r0g) S[j][0] = -1e30f;
                if (c1 > r0g) S[j][1] = -1e30f;
                if (c0 > r1g) S[j][2] = -1e30f;
                if (c1 > r1g) S[j][3] = -1e30f;
            }
        }

        // ---- online softmax on fragments (rows r0, r1 per thread) ----
        float mx0 = -1e30f, mx1 = -1e30f;
        #pragma unroll
        for (int j = 0; j < 8; j++) {
            mx0 = fmaxf(mx0, fmaxf(S[j][0], S[j][1]));
            mx1 = fmaxf(mx1, fmaxf(S[j][2], S[j][3]));
        }
        mx0 = fmaxf(mx0, __shfl_xor_sync(0xffffffffu, mx0, 1));
        mx0 = fmaxf(mx0, __shfl_xor_sync(0xffffffffu, mx0, 2));
        mx1 = fmaxf(mx1, __shfl_xor_sync(0xffffffffu, mx1, 1));
        mx1 = fmaxf(mx1, __shfl_xor_sync(0xffffffffu, mx1, 2));

        const float mn0 = fmaxf(m_run[0], mx0);
        const float mn1 = fmaxf(m_run[1], mx1);
        const float al0 = __expf(m_run[0] - mn0);
        const float al1 = __expf(m_run[1] - mn1);
        float sum0 = 0.0f, sum1 = 0.0f;
        #pragma unroll
        for (int j = 0; j < 8; j++) {
            S[j][0] = __expf(S[j][0] - mn0); sum0 += S[j][0];
            S[j][1] = __expf(S[j][1] - mn0); sum0 += S[j][1];
            S[j][2] = __expf(S[j][2] - mn1); sum1 += S[j][2];
            S[j][3] = __expf(S[j][3] - mn1); sum1 += S[j][3];
        }
        sum0 += __shfl_xor_sync(0xffffffffu, sum0, 1);
        sum0 += __shfl_xor_sync(0xffffffffu, sum0, 2);
        sum1 += __shfl_xor_sync(0xffffffffu, sum1, 1);
        sum1 += __shfl_xor_sync(0xffffffffu, sum1, 2);

        l_run[0] = l_run[0] * al0 + sum0;  m_run[0] = mn0;
        l_run[1] = l_run[1] * al1 + sum1;  m_run[1] = mn1;

        #pragma unroll
        for (int j = 0; j < 8; j++) {
            Z[j][0] *= al0; Z[j][1] *= al0;
            Z[j][2] *= al1; Z[j][3] *= al1;
        }

        // ---- Z += P V : repack S c-frags into a-frags (pure register) ----
        #pragma unroll
        for (int jj = 0; jj < 4; jj++) {
            uint32_t a[4];
            a[0] = pack_h2(S[2*jj][0],     S[2*jj][1]);
            a[1] = pack_h2(S[2*jj][2],     S[2*jj][3]);
            a[2] = pack_h2(S[2*jj + 1][0], S[2*jj + 1][1]);
            a[3] = pack_h2(S[2*jj + 1][2], S[2*jj + 1][3]);
            const int kc = jj * 16 + kq;
            #pragma unroll
            for (int j = 0; j < 8; j++) {
                const int nrow = j * 8 + g;
                const uint32_t bb0 = *(const uint32_t*)&Vs[nrow * QSTR + kc];
                const uint32_t bb1 = *(const uint32_t*)&Vs[nrow * QSTR + kc + 8];
                mma_f16(Z[j], a, bb0, bb1);
            }
        }
        __syncthreads();
    }

    // ---- epilogue: normalize + split-bf16 Z ----
    const float inv0 = 1.0f / l_run[0];
    const float inv1 = 1.0f / l_run[1];
    const int r0 = q0 + w * 16 + g, r1 = r0 + 8;
    #pragma unroll
    for (int j = 0; j < 8; j++) {
        const int col = h * 64 + j * 8 + kq;
        const size_t i0 = (size_t)(b * SEQ + r0) * DMODEL + col;
        const size_t i1 = (size_t)(b * SEQ + r1) * DMODEL + col;
        __nv_bfloat16 hi, lo;
        bf16_split(Z[j][0] * inv0, hi, lo); g_Zh[i0]     = hi; g_Zl[i0]     = lo;
        bf16_split(Z[j][1] * inv0, hi, lo); g_Zh[i0 + 1] = hi; g_Zl[i0 + 1] = lo;
        bf16_split(Z[j][2] * inv1, hi, lo); g_Zh[i1]     = hi; g_Zl[i1]     = lo;
        bf16_split(Z[j][3] * inv1, hi, lo); g_Zh[i1 + 1] = hi; g_Zl[i1 + 1] = lo;
    }
}

// ------------------------------ launch --------------------------------------
extern "C" void kernel_launch(void* const* d_in, const int* in_sizes, int n_in,
                              void* d_out, int out_size)
{
    (void)in_sizes; (void)n_in; (void)out_size;
    const float* x  = (const float*)d_in[0];
    const float* Wq = (const float*)d_in[1];
    const float* Wk = (const float*)d_in[2];
    const float* Wv = (const float*)d_in[3];
    const float* Wo = (const float*)d_in[4];
    const float* bq = (const float*)d_in[5];
    const float* bk = (const float*)d_in[6];
    const float* bv = (const float*)d_in[7];
    const float* bo = (const float*)d_in[8];
    float* out = (float*)d_out;

    cudaFuncSetAttribute(gemm_kernel,
                         cudaFuncAttributeMaxDynamicSharedMemorySize, GSMEM);

    convert_x_kernel<<<(MROWS * DMODEL / 2) / 256, 256>>>(x);
    transpose_wqkv<<<dim3(32, 2, 48), 256>>>(Wq, Wk, Wv);
    transpose_wo<<<dim3(32, 32), 256>>>(Wo);

    gemm_kernel<<<dim3(24, 32), 256, GSMEM>>>(bq, bk, bv, nullptr, 0);

    attn_kernel<<<dim3(SEQ / 128, NHEADS, BATCH), 256>>>();

    gemm_kernel<<<dim3(8, 32), 256, GSMEM>>>(bo, bo, bo, out, 1);
}